// round 4
// baseline (speedup 1.0000x reference)
// R4: k_adds uses fma.rn.f32x2 on j-pair-packed smem records with G/Gs split
// across warp halves; k_sel rewritten as per-batch smem radix-select. Rest as R3.
#include <cuda_runtime.h>
#include <math.h>

#define BB 4
#define NN 2048
#define MM 4096
#define FARV 100000.0f

typedef unsigned long long u64;

// ---------------- scratch (device globals; no allocation) ----------------
__device__ float4 g_pc4[BB*MM];          // contact points + norm
__device__ float  g_pos[BB*NN];          // success flag
__device__ float  g_pri[BB*NN];          // priority (r for negatives, +inf for positives)
__device__ float  g_wlab[BB*NN];         // gathered width label
__device__ float4 g_rec[BB*NN*4];        // per point: (R row0,t0)(R row1,t1)(R row2,t2)(gn,gsn,0,0)
__device__ double g_acc[BB*8];           // 0 posSum, 1 bceSum, 2 selSum, 3 wlSum, 4 addsSum

__constant__ float c_lo[10] = {0.0f, 0.00794435329f, 0.0158887021f, 0.0238330509f, 0.0317773996f,
                               0.0397217484f, 0.0476660972f, 0.0556104459f, 0.0635547947f, 0.0714991435f};
__constant__ float c_hi[10] = {0.00794435329f, 0.0158887021f, 0.0238330509f, 0.0317773996f, 0.0397217484f,
                               0.0476660972f, 0.0556104459f, 0.0635547947f, 0.0714991435f, 0.08f};
__constant__ float c_wt[10] = {0.16652107f, 0.21488856f, 0.37031708f, 0.55618503f, 0.75124664f,
                               0.93943357f, 1.07824539f, 1.19423112f, 1.55731375f, 2.34173634f};

// ---------------- f32x2 packed helpers (sm_103a) ----------------
__device__ __forceinline__ u64 pk2(float lo, float hi){
  u64 r; asm("mov.b64 %0, {%1,%2};" : "=l"(r) : "f"(lo), "f"(hi)); return r;
}
__device__ __forceinline__ u64 ffma2(u64 a, u64 b, u64 c){
  u64 d; asm("fma.rn.f32x2 %0, %1, %2, %3;" : "=l"(d) : "l"(a), "l"(b), "l"(c)); return d;
}
__device__ __forceinline__ u64 fadd2(u64 a, u64 b){
  u64 d; asm("add.rn.f32x2 %0, %1, %2;" : "=l"(d) : "l"(a), "l"(b)); return d;
}
__device__ __forceinline__ void up2(u64 v, float& lo, float& hi){
  asm("mov.b64 {%0,%1}, %2;" : "=f"(lo), "=f"(hi) : "l"(v));
}

// ---------------- threefry2x32 (JAX-exact, key(42), counts = iota(8192)) ----------------
__device__ __forceinline__ unsigned rotl32(unsigned x, unsigned d){ return (x<<d)|(x>>(32u-d)); }

__device__ __forceinline__ float threefry_uniform_8192(unsigned flat){
  unsigned c0, c1; bool second;
  if (flat < 4096u){ c0 = flat;        c1 = flat + 4096u; second = false; }
  else             { c0 = flat - 4096u; c1 = flat;        second = true;  }
  const unsigned ks0 = 0u, ks1 = 42u, ks2 = 0u ^ 42u ^ 0x1BD11BDAu;
  unsigned x0 = c0 + ks0, x1 = c1 + ks1;
#define TF_ROUND(r) { x0 += x1; x1 = rotl32(x1,(r)); x1 ^= x0; }
  TF_ROUND(13) TF_ROUND(15) TF_ROUND(26) TF_ROUND(6)
  x0 += ks1; x1 += ks2 + 1u;
  TF_ROUND(17) TF_ROUND(29) TF_ROUND(16) TF_ROUND(24)
  x0 += ks2; x1 += ks0 + 2u;
  TF_ROUND(13) TF_ROUND(15) TF_ROUND(26) TF_ROUND(6)
  x0 += ks0; x1 += ks1 + 3u;
  TF_ROUND(17) TF_ROUND(29) TF_ROUND(16) TF_ROUND(24)
  x0 += ks1; x1 += ks2 + 4u;
  TF_ROUND(13) TF_ROUND(15) TF_ROUND(26) TF_ROUND(6)
  x0 += ks2; x1 += ks0 + 5u;
#undef TF_ROUND
  unsigned bits = second ? x1 : x0;
  float f = __uint_as_float((bits >> 9) | 0x3F800000u) - 1.0f;
  return fmaxf(f, 0.0f);
}

// ---------------- K0: prep contact float4 + zero accumulators ----------------
__global__ void k_prep(const float* __restrict__ pcp){
  int i = blockIdx.x*blockDim.x + threadIdx.x;
  if (i < BB*8) g_acc[i] = 0.0;
  if (i < BB*MM){
    float x = pcp[i*3+0], y = pcp[i*3+1], z = pcp[i*3+2];
    g_pc4[i] = make_float4(x, y, z, x*x + y*y + z*z);
  }
}

// ---------------- K1: nearest neighbor + threefry + (R,t,gn,gsn) record ----------------
__global__ __launch_bounds__(256) void k_nn(
    const float* __restrict__ pred_points,
    const float* __restrict__ pcw,
    const float* __restrict__ pcr,
    const float* __restrict__ pct,
    const float* __restrict__ cp,
    const float* __restrict__ cps)
{
  __shared__ float s_cp[15], s_cps[15];
  __shared__ float s_psum[8];
  int tid = threadIdx.x, lane = tid & 31, warp = tid >> 5;
  if (tid < 15){ s_cp[tid] = cp[tid]; s_cps[tid] = cps[tid]; }
  __syncthreads();

  int q0 = (blockIdx.x*8 + warp)*4;
  int b  = q0 / NN;

  float qx[4], qy[4], qz[4], qn[4];
#pragma unroll
  for (int k = 0; k < 4; k++){
    const float* p = pred_points + (size_t)(q0+k)*3;
    qx[k]=p[0]; qy[k]=p[1]; qz[k]=p[2];
    qn[k]=qx[k]*qx[k]+qy[k]*qy[k]+qz[k]*qz[k];
  }
  float best[4] = {3.4e38f,3.4e38f,3.4e38f,3.4e38f};
  int   bidx[4] = {0,0,0,0};
  const float4* pc = g_pc4 + (size_t)b*MM;
  for (int j = lane; j < MM; j += 32){
    float4 c = pc[j];
#pragma unroll
    for (int k = 0; k < 4; k++){
      float dot = qx[k]*c.x + qy[k]*c.y + qz[k]*c.z;
      float d = qn[k] + c.w - 2.0f*dot;
      d = fmaxf(d, 0.0f);
      if (d < best[k]){ best[k] = d; bidx[k] = j; }
    }
  }
#pragma unroll
  for (int k = 0; k < 4; k++){
#pragma unroll
    for (int off = 16; off; off >>= 1){
      float ov = __shfl_xor_sync(0xffffffffu, best[k], off);
      int   oi = __shfl_xor_sync(0xffffffffu, bidx[k], off);
      if (ov < best[k] || (ov == best[k] && oi < bidx[k])){ best[k]=ov; bidx[k]=oi; }
    }
  }

  float myPos = 0.0f;
  if (lane < 4){
    int k = lane;
    int q = q0 + k;
    int mi = bidx[k];
    float success = (best[k] < 2.5e-5f) ? 1.0f : 0.0f;  // RADIUS^2
    myPos = success;
    g_pos[q]  = success;
    g_wlab[q] = pcw[(size_t)b*MM + mi];
    float r = threefry_uniform_8192((unsigned)q);
    g_pri[q] = (success > 0.5f) ? __int_as_float(0x7f800000) : r;

    float Rm[9], Tv[3];
    if (success > 0.5f){
      const float* rp = pcr + ((size_t)b*MM + mi)*9;
#pragma unroll
      for (int u = 0; u < 9; u++) Rm[u] = rp[u];
      const float* tp = pct + ((size_t)b*MM + mi)*3;
      Tv[0]=tp[0]; Tv[1]=tp[1]; Tv[2]=tp[2];
    } else {
#pragma unroll
      for (int u = 0; u < 9; u++) Rm[u] = FARV;
      Tv[0]=FARV; Tv[1]=FARV; Tv[2]=FARV;
    }
    float gn = 0.0f, gsn = 0.0f;
#pragma unroll
    for (int c = 0; c < 5; c++){
#pragma unroll
      for (int d = 0; d < 3; d++){
        float v  = Rm[d*3+0]*s_cp [c*3+0] + Rm[d*3+1]*s_cp [c*3+1] + Rm[d*3+2]*s_cp [c*3+2] + Tv[d];
        float vs = Rm[d*3+0]*s_cps[c*3+0] + Rm[d*3+1]*s_cps[c*3+1] + Rm[d*3+2]*s_cps[c*3+2] + Tv[d];
        gn  += v*v;
        gsn += vs*vs;
      }
    }
    float4* rec = g_rec + (size_t)q*4;
    rec[0] = make_float4(Rm[0], Rm[1], Rm[2], Tv[0]);
    rec[1] = make_float4(Rm[3], Rm[4], Rm[5], Tv[1]);
    rec[2] = make_float4(Rm[6], Rm[7], Rm[8], Tv[2]);
    rec[3] = make_float4(gn, gsn, 0.0f, 0.0f);
  }

  float ps = myPos;
#pragma unroll
  for (int off = 16; off; off >>= 1) ps += __shfl_xor_sync(0xffffffffu, ps, off);
  if (lane == 0) s_psum[warp] = ps;
  __syncthreads();
  if (tid == 0){
    double t = 0.0;
    for (int w = 0; w < 8; w++) t += (double)s_psum[w];
    atomicAdd(&g_acc[b*8+0], t);
  }
}

// ---------------- K2: radix-select hard-negative mining + bce + width loss ----------------
// one block (256 threads) per batch; keys in smem; exact k-th smallest with
// index-order tie-breaking == stable argsort rank semantics.
__global__ __launch_bounds__(256) void k_sel(
    const float* __restrict__ scores,
    const float* __restrict__ gwh)
{
  __shared__ unsigned s_key[NN];      // 8KB
  __shared__ unsigned s_hist[256];
  __shared__ unsigned s_bin, s_rem;
  __shared__ float    s_red[3][8];
  int b = blockIdx.x;
  int tid = threadIdx.x, lane = tid & 31, warp = tid >> 5;

  for (int i = tid; i < NN; i += 256){
    float pos = g_pos[(size_t)b*NN + i];
    float pri = g_pri[(size_t)b*NN + i];
    s_key[i] = (pos > 0.5f) ? 0xFFFFFFFFu : __float_as_uint(pri);
  }
  __syncthreads();

  double nPos = g_acc[b*8+0];
  unsigned kk = (nPos > 0.0) ? (unsigned)nPos : 2u;

  unsigned prefix = 0, prefmask = 0, krem = kk;
#pragma unroll
  for (int pass = 0; pass < 4; pass++){
    int shift = 24 - pass*8;
    s_hist[tid] = 0;
    __syncthreads();
    for (int i = tid; i < NN; i += 256){
      unsigned key = s_key[i];
      if ((key & prefmask) == prefix) atomicAdd(&s_hist[(key >> shift) & 0xFFu], 1u);
    }
    __syncthreads();
    if (tid < 32){
      unsigned loc[8]; unsigned tot = 0;
#pragma unroll
      for (int u = 0; u < 8; u++){ loc[u] = s_hist[tid*8+u]; tot += loc[u]; }
      unsigned sc = tot;
#pragma unroll
      for (int off = 1; off < 32; off <<= 1){
        unsigned v = __shfl_up_sync(0xffffffffu, sc, off);
        if (lane >= off) sc += v;
      }
      unsigned excl = sc - tot;
      bool has = (excl < krem) && (krem <= sc);
      unsigned msk = __ballot_sync(0xffffffffu, has);
      int src = __ffs(msk) - 1;
      if (tid == src){
        unsigned cum = excl; unsigned bin = tid*8;
#pragma unroll
        for (int u = 0; u < 8; u++){
          if (cum + loc[u] >= krem){ bin = tid*8+u; break; }
          cum += loc[u];
        }
        s_bin = bin; s_rem = krem - cum;
      }
    }
    __syncthreads();
    unsigned bin = s_bin;
    krem = s_rem;
    prefix |= bin << shift;
    prefmask |= 0xFFu << shift;
    __syncthreads();
  }
  unsigned t = prefix;
  unsigned rem = krem;   // ties at t to select (index order)

  // fused selection + bce + width loss
  float bcesum = 0.0f, selsum = 0.0f, wlsum = 0.0f;
  for (int i = tid; i < NN; i += 256){
    size_t gi = (size_t)b*NN + i;
    float pos = g_pos[gi];
    unsigned key = s_key[i];
    float sel;
    if (pos > 0.5f){
      sel = 1.0f;
    } else if (key < t){
      sel = 1.0f;
    } else if (key == t){
      unsigned tr = 0;
      for (int j = 0; j < i; j++) if (s_key[j] == t) tr++;
      sel = (tr < rem) ? 1.0f : 0.0f;
    } else {
      sel = 0.0f;
    }
    float p = scores[gi];
    p = fminf(fmaxf(p, 1e-7f), 1.0f - 1e-7f);
    float bce = -(pos*logf(p) + (1.0f - pos)*logf(1.0f - p));
    bcesum += bce*sel;
    selsum += sel;

    if (pos > 0.5f){
      float w = g_wlab[gi];
      float acc = 0.0f;
#pragma unroll
      for (int kb = 0; kb < 10; kb++){
        float mh = (w >= c_lo[kb] && w < c_hi[kb]) ? 1.0f : 0.0f;
        float x = gwh[(size_t)b*10*NN + (size_t)kb*NN + i];
        float bw = fmaxf(x, 0.0f) - x*mh + log1pf(expf(-fabsf(x)));
        acc += c_wt[kb]*bw;
      }
      wlsum += acc * 0.1f;
    }
  }
#pragma unroll
  for (int off = 16; off; off >>= 1){
    bcesum += __shfl_xor_sync(0xffffffffu, bcesum, off);
    selsum += __shfl_xor_sync(0xffffffffu, selsum, off);
    wlsum  += __shfl_xor_sync(0xffffffffu, wlsum , off);
  }
  if (lane == 0){ s_red[0][warp]=bcesum; s_red[1][warp]=selsum; s_red[2][warp]=wlsum; }
  __syncthreads();
  if (tid == 0){
    double a=0, c=0, d=0;
    for (int w = 0; w < 8; w++){ a += (double)s_red[0][w]; c += (double)s_red[1][w]; d += (double)s_red[2][w]; }
    g_acc[b*8+1] = a;
    g_acc[b*8+2] = c;
    g_acc[b*8+3] = d;
  }
}

// ---------------- K3: ADD-S, f32x2-packed j-pairs, G/Gs split across warps ----------------
// Block = 256 threads (8 warps). Warps 0-3 compute G-variant mins, warps 4-7 Gs,
// for the same 16 queries (warp w handles queries iBase + (w&3)*4 .. +3).
// smem tile: 128 j-pairs × 9 ulonglong2 (144B stride); u64 at comp c holds
// (comp_c(j0), comp_c(j1)). comps 0..11 = (R|t) interleaved, 12=gn, 13=gsn.
#define JT 256
__global__ __launch_bounds__(256) void k_adds(
    const float* __restrict__ grasps,
    const float* __restrict__ scores,
    const float* __restrict__ cp,
    const float* __restrict__ cps)
{
  __shared__ ulonglong2 sP[(JT/2)*9];
  __shared__ float s_cp[15], s_cps[15];
  __shared__ float s_mG[16], s_mGs[16], s_ctr[16];

  int tid = threadIdx.x, lane = tid & 31, warp = tid >> 5;
  if (tid < 15){ s_cp[tid] = cp[tid]; s_cps[tid] = cps[tid]; }
  __syncthreads();

  int iBase = blockIdx.x*16;
  int b  = iBase / NN;
  int variant = warp >> 2;          // 0 = G (uses cp coeffs, gn), 1 = Gs (cps, gsn)
  int qg = warp & 3;
  int i0 = iBase + qg*4;
  const float* se = variant ? s_cps : s_cp;

  // packed (broadcast) query features: A2[q][c] pairs with record comp c
  u64 A2[4][12]; u64 pn2[4];
#pragma unroll
  for (int q = 0; q < 4; q++){
    const float* gm = grasps + (size_t)(i0+q)*16;
    float P[15]; float pq = 0.0f;
#pragma unroll
    for (int c = 0; c < 5; c++)
#pragma unroll
      for (int d = 0; d < 3; d++){
        float v = gm[d*4+0]*s_cp[c*3+0] + gm[d*4+1]*s_cp[c*3+1] + gm[d*4+2]*s_cp[c*3+2] + gm[d*4+3];
        P[c*3+d] = v; pq += v*v;
      }
    pn2[q] = pk2(pq, pq);
#pragma unroll
    for (int d = 0; d < 3; d++){
      float s0=0, s1=0, s2=0, sp=0;
#pragma unroll
      for (int c = 0; c < 5; c++){
        float pv = P[c*3+d];
        s0 += pv*se[c*3+0]; s1 += pv*se[c*3+1]; s2 += pv*se[c*3+2];
        sp += pv;
      }
      A2[q][d*4+0]=pk2(s0,s0); A2[q][d*4+1]=pk2(s1,s1);
      A2[q][d*4+2]=pk2(s2,s2); A2[q][d*4+3]=pk2(sp,sp);
    }
  }

  const u64 neg2 = 0xC0000000C0000000ull;  // (-2.0f, -2.0f)
  float m[4] = {3.4e38f, 3.4e38f, 3.4e38f, 3.4e38f};

  for (int t = 0; t < NN/JT; t++){
    __syncthreads();
    int jb = t*JT;
    // loader: each thread repacks one j into pair-interleaved layout
    {
      int j = tid;                               // 0..255
      const float4* rp = g_rec + ((size_t)b*NN + jb + j)*4;
      float4 r0 = rp[0], r1 = rp[1], r2 = rp[2], r3 = rp[3];
      float* dst = (float*)sP + (j>>1)*36 + (j&1);
      dst[0]=r0.x;  dst[2]=r0.y;  dst[4]=r0.z;  dst[6]=r0.w;
      dst[8]=r1.x;  dst[10]=r1.y; dst[12]=r1.z; dst[14]=r1.w;
      dst[16]=r2.x; dst[18]=r2.y; dst[20]=r2.z; dst[22]=r2.w;
      dst[24]=r3.x; dst[26]=r3.y;   // gn, gsn
    }
    __syncthreads();
#pragma unroll
    for (int u = 0; u < JT/64; u++){
      int p = lane + u*32;
      const ulonglong2* row = sP + p*9;
      ulonglong2 v0 = row[0], v1 = row[1], v2 = row[2];
      ulonglong2 v3 = row[3], v4 = row[4], v5 = row[5];
      ulonglong2 v6 = row[6];
      u64 gpair = variant ? v6.y : v6.x;
#pragma unroll
      for (int q = 0; q < 4; q++){
        u64 acc = ffma2(A2[q][0],  v0.x, 0ull);
        acc = ffma2(A2[q][1],  v0.y, acc);
        acc = ffma2(A2[q][2],  v1.x, acc);
        acc = ffma2(A2[q][3],  v1.y, acc);
        acc = ffma2(A2[q][4],  v2.x, acc);
        acc = ffma2(A2[q][5],  v2.y, acc);
        acc = ffma2(A2[q][6],  v3.x, acc);
        acc = ffma2(A2[q][7],  v3.y, acc);
        acc = ffma2(A2[q][8],  v4.x, acc);
        acc = ffma2(A2[q][9],  v4.y, acc);
        acc = ffma2(A2[q][10], v5.x, acc);
        acc = ffma2(A2[q][11], v5.y, acc);
        u64 d2 = ffma2(neg2, acc, fadd2(pn2[q], gpair));
        float dlo, dhi; up2(d2, dlo, dhi);
        m[q] = fminf(m[q], fminf(dlo, dhi));
      }
    }
  }
#pragma unroll
  for (int q = 0; q < 4; q++)
#pragma unroll
    for (int off = 16; off; off >>= 1)
      m[q] = fminf(m[q], __shfl_xor_sync(0xffffffffu, m[q], off));

  if (lane == 0){
    float* dst = variant ? s_mGs : s_mG;
#pragma unroll
    for (int q = 0; q < 4; q++) dst[qg*4+q] = m[q];
  }
  __syncthreads();
  if (tid < 16){
    int i = iBase + tid;
    float mm = fminf(s_mG[tid], s_mGs[tid]);
    s_ctr[tid] = g_pos[i] * sqrtf(fmaxf(mm, 0.0f) + 1e-12f) * scores[i];
  }
  __syncthreads();
  if (tid == 0){
    double a = 0.0;
    for (int w = 0; w < 16; w++) a += (double)s_ctr[w];
    atomicAdd(&g_acc[b*8+4], a);
  }
}

// ---------------- K4: finalize ----------------
__global__ void k_fin(float* __restrict__ out, int out_size){
  double bin = 0.0, wid = 0.0, adds = 0.0;
  for (int b = 0; b < BB; b++){
    double posSum = g_acc[b*8+0];
    double piv = fmax(posSum, 1.0);
    bin  += g_acc[b*8+1] / fmax(g_acc[b*8+2], 1.0);
    wid  += g_acc[b*8+3] / piv;
    adds += g_acc[b*8+4] / piv;
  }
  bin /= BB; wid /= BB; adds /= BB;
  double total = bin + wid + 3.0*adds;
  if (out_size > 0) out[0] = (float)total;
  if (out_size > 1) out[1] = (float)bin;
  if (out_size > 2) out[2] = (float)wid;
  if (out_size > 3) out[3] = (float)adds;
}

extern "C" void kernel_launch(void* const* d_in, const int* in_sizes, int n_in,
                              void* d_out, int out_size){
  const float* pred_grasps = (const float*)d_in[0];   // (4,2048,4,4)
  const float* pred_scores = (const float*)d_in[1];   // (4,2048,1)
  const float* pred_points = (const float*)d_in[2];   // (4,2048,3)
  const float* gwh         = (const float*)d_in[3];   // (4,10,2048)
  const float* pcp         = (const float*)d_in[4];   // (4,4096,3)
  const float* pcw         = (const float*)d_in[5];   // (4,4096)
  const float* pcr         = (const float*)d_in[6];   // (4,4096,3,3)
  const float* pct         = (const float*)d_in[7];   // (4,4096,3)
  const float* cp          = (const float*)d_in[8];   // (1,5,3)
  const float* cps         = (const float*)d_in[9];   // (1,5,3)

  k_prep<<<64, 256>>>(pcp);
  k_nn  <<<BB*NN/32, 256>>>(pred_points, pcw, pcr, pct, cp, cps);
  k_sel <<<BB, 256>>>(pred_scores, gwh);
  k_adds<<<BB*NN/16, 256>>>(pred_grasps, pred_scores, cp, cps);
  k_fin <<<1, 1>>>((float*)d_out, out_size);
}

// round 5
// speedup vs baseline: 1.2216x; 1.2216x over previous
// R5: k_adds reverted to the proven R3 scalar-FFMA version (R4's f32x2 split
// raised smem traffic 1.75x and lost ILP). k_sel keeps the radix-select but at
// 512 threads/block to cut its latency. Rest identical to R3.
#include <cuda_runtime.h>
#include <math.h>

#define BB 4
#define NN 2048
#define MM 4096
#define FARV 100000.0f

// ---------------- scratch (device globals; no allocation) ----------------
__device__ float4 g_pc4[BB*MM];          // contact points + norm
__device__ float  g_pos[BB*NN];          // success flag
__device__ float  g_pri[BB*NN];          // priority (r for negatives, +inf for positives)
__device__ float  g_wlab[BB*NN];         // gathered width label
__device__ float4 g_rec[BB*NN*4];        // per point: (R row0,t0)(R row1,t1)(R row2,t2)(gn,gsn,0,0)
__device__ double g_acc[BB*8];           // 0 posSum, 1 bceSum, 2 selSum, 3 wlSum, 4 addsSum

__constant__ float c_lo[10] = {0.0f, 0.00794435329f, 0.0158887021f, 0.0238330509f, 0.0317773996f,
                               0.0397217484f, 0.0476660972f, 0.0556104459f, 0.0635547947f, 0.0714991435f};
__constant__ float c_hi[10] = {0.00794435329f, 0.0158887021f, 0.0238330509f, 0.0317773996f, 0.0397217484f,
                               0.0476660972f, 0.0556104459f, 0.0635547947f, 0.0714991435f, 0.08f};
__constant__ float c_wt[10] = {0.16652107f, 0.21488856f, 0.37031708f, 0.55618503f, 0.75124664f,
                               0.93943357f, 1.07824539f, 1.19423112f, 1.55731375f, 2.34173634f};

// ---------------- threefry2x32 (JAX-exact, key(42), counts = iota(8192)) ----------------
__device__ __forceinline__ unsigned rotl32(unsigned x, unsigned d){ return (x<<d)|(x>>(32u-d)); }

__device__ __forceinline__ float threefry_uniform_8192(unsigned flat){
  unsigned c0, c1; bool second;
  if (flat < 4096u){ c0 = flat;        c1 = flat + 4096u; second = false; }
  else             { c0 = flat - 4096u; c1 = flat;        second = true;  }
  const unsigned ks0 = 0u, ks1 = 42u, ks2 = 0u ^ 42u ^ 0x1BD11BDAu;
  unsigned x0 = c0 + ks0, x1 = c1 + ks1;
#define TF_ROUND(r) { x0 += x1; x1 = rotl32(x1,(r)); x1 ^= x0; }
  TF_ROUND(13) TF_ROUND(15) TF_ROUND(26) TF_ROUND(6)
  x0 += ks1; x1 += ks2 + 1u;
  TF_ROUND(17) TF_ROUND(29) TF_ROUND(16) TF_ROUND(24)
  x0 += ks2; x1 += ks0 + 2u;
  TF_ROUND(13) TF_ROUND(15) TF_ROUND(26) TF_ROUND(6)
  x0 += ks0; x1 += ks1 + 3u;
  TF_ROUND(17) TF_ROUND(29) TF_ROUND(16) TF_ROUND(24)
  x0 += ks1; x1 += ks2 + 4u;
  TF_ROUND(13) TF_ROUND(15) TF_ROUND(26) TF_ROUND(6)
  x0 += ks2; x1 += ks0 + 5u;
#undef TF_ROUND
  unsigned bits = second ? x1 : x0;
  float f = __uint_as_float((bits >> 9) | 0x3F800000u) - 1.0f;
  return fmaxf(f, 0.0f);
}

// ---------------- K0: prep contact float4 + zero accumulators ----------------
__global__ void k_prep(const float* __restrict__ pcp){
  int i = blockIdx.x*blockDim.x + threadIdx.x;
  if (i < BB*8) g_acc[i] = 0.0;
  if (i < BB*MM){
    float x = pcp[i*3+0], y = pcp[i*3+1], z = pcp[i*3+2];
    g_pc4[i] = make_float4(x, y, z, x*x + y*y + z*z);
  }
}

// ---------------- K1: nearest neighbor + threefry + (R,t,gn,gsn) record ----------------
// warp handles 4 queries; block = 8 warps = 32 queries (batch-aligned)
__global__ __launch_bounds__(256) void k_nn(
    const float* __restrict__ pred_points,
    const float* __restrict__ pcw,
    const float* __restrict__ pcr,
    const float* __restrict__ pct,
    const float* __restrict__ cp,
    const float* __restrict__ cps)
{
  __shared__ float s_cp[15], s_cps[15];
  __shared__ float s_psum[8];
  int tid = threadIdx.x, lane = tid & 31, warp = tid >> 5;
  if (tid < 15){ s_cp[tid] = cp[tid]; s_cps[tid] = cps[tid]; }
  __syncthreads();

  int q0 = (blockIdx.x*8 + warp)*4;
  int b  = q0 / NN;

  float qx[4], qy[4], qz[4], qn[4];
#pragma unroll
  for (int k = 0; k < 4; k++){
    const float* p = pred_points + (size_t)(q0+k)*3;
    qx[k]=p[0]; qy[k]=p[1]; qz[k]=p[2];
    qn[k]=qx[k]*qx[k]+qy[k]*qy[k]+qz[k]*qz[k];
  }
  float best[4] = {3.4e38f,3.4e38f,3.4e38f,3.4e38f};
  int   bidx[4] = {0,0,0,0};
  const float4* pc = g_pc4 + (size_t)b*MM;
  for (int j = lane; j < MM; j += 32){
    float4 c = pc[j];
#pragma unroll
    for (int k = 0; k < 4; k++){
      float dot = qx[k]*c.x + qy[k]*c.y + qz[k]*c.z;
      float d = qn[k] + c.w - 2.0f*dot;
      d = fmaxf(d, 0.0f);
      if (d < best[k]){ best[k] = d; bidx[k] = j; }
    }
  }
#pragma unroll
  for (int k = 0; k < 4; k++){
#pragma unroll
    for (int off = 16; off; off >>= 1){
      float ov = __shfl_xor_sync(0xffffffffu, best[k], off);
      int   oi = __shfl_xor_sync(0xffffffffu, bidx[k], off);
      if (ov < best[k] || (ov == best[k] && oi < bidx[k])){ best[k]=ov; bidx[k]=oi; }
    }
  }

  float myPos = 0.0f;
  if (lane < 4){
    int k = lane;
    int q = q0 + k;
    int mi = bidx[k];
    float success = (best[k] < 2.5e-5f) ? 1.0f : 0.0f;  // RADIUS^2
    myPos = success;
    g_pos[q]  = success;
    g_wlab[q] = pcw[(size_t)b*MM + mi];
    float r = threefry_uniform_8192((unsigned)q);
    g_pri[q] = (success > 0.5f) ? __int_as_float(0x7f800000) : r;

    float Rm[9], Tv[3];
    if (success > 0.5f){
      const float* rp = pcr + ((size_t)b*MM + mi)*9;
#pragma unroll
      for (int u = 0; u < 9; u++) Rm[u] = rp[u];
      const float* tp = pct + ((size_t)b*MM + mi)*3;
      Tv[0]=tp[0]; Tv[1]=tp[1]; Tv[2]=tp[2];
    } else {
#pragma unroll
      for (int u = 0; u < 9; u++) Rm[u] = FARV;
      Tv[0]=FARV; Tv[1]=FARV; Tv[2]=FARV;
    }
    float gn = 0.0f, gsn = 0.0f;
#pragma unroll
    for (int c = 0; c < 5; c++){
#pragma unroll
      for (int d = 0; d < 3; d++){
        float v  = Rm[d*3+0]*s_cp [c*3+0] + Rm[d*3+1]*s_cp [c*3+1] + Rm[d*3+2]*s_cp [c*3+2] + Tv[d];
        float vs = Rm[d*3+0]*s_cps[c*3+0] + Rm[d*3+1]*s_cps[c*3+1] + Rm[d*3+2]*s_cps[c*3+2] + Tv[d];
        gn  += v*v;
        gsn += vs*vs;
      }
    }
    float4* rec = g_rec + (size_t)q*4;
    rec[0] = make_float4(Rm[0], Rm[1], Rm[2], Tv[0]);
    rec[1] = make_float4(Rm[3], Rm[4], Rm[5], Tv[1]);
    rec[2] = make_float4(Rm[6], Rm[7], Rm[8], Tv[2]);
    rec[3] = make_float4(gn, gsn, 0.0f, 0.0f);
  }

  float ps = myPos;
#pragma unroll
  for (int off = 16; off; off >>= 1) ps += __shfl_xor_sync(0xffffffffu, ps, off);
  if (lane == 0) s_psum[warp] = ps;
  __syncthreads();
  if (tid == 0){
    double t = 0.0;
    for (int w = 0; w < 8; w++) t += (double)s_psum[w];
    atomicAdd(&g_acc[b*8+0], t);
  }
}

// ---------------- K2: radix-select hard-negative mining + bce + width loss ----------------
// one block (512 threads) per batch; keys in smem; exact k-th smallest with
// index-order tie-breaking == stable argsort rank semantics.
__global__ __launch_bounds__(512) void k_sel(
    const float* __restrict__ scores,
    const float* __restrict__ gwh)
{
  __shared__ unsigned s_key[NN];      // 8KB
  __shared__ unsigned s_hist[256];
  __shared__ unsigned s_bin, s_rem;
  __shared__ float    s_red[3][16];
  int b = blockIdx.x;
  int tid = threadIdx.x, lane = tid & 31, warp = tid >> 5;

  for (int i = tid; i < NN; i += 512){
    float pos = g_pos[(size_t)b*NN + i];
    float pri = g_pri[(size_t)b*NN + i];
    s_key[i] = (pos > 0.5f) ? 0xFFFFFFFFu : __float_as_uint(pri);
  }
  if (tid < 256) s_hist[tid] = 0;
  __syncthreads();

  double nPos = g_acc[b*8+0];
  unsigned kk = (nPos > 0.0) ? (unsigned)nPos : 2u;

  unsigned prefix = 0, prefmask = 0, krem = kk;
#pragma unroll
  for (int pass = 0; pass < 4; pass++){
    int shift = 24 - pass*8;
    for (int i = tid; i < NN; i += 512){
      unsigned key = s_key[i];
      if ((key & prefmask) == prefix) atomicAdd(&s_hist[(key >> shift) & 0xFFu], 1u);
    }
    __syncthreads();
    if (tid < 32){
      unsigned loc[8]; unsigned tot = 0;
#pragma unroll
      for (int u = 0; u < 8; u++){ loc[u] = s_hist[tid*8+u]; tot += loc[u]; }
      unsigned sc = tot;
#pragma unroll
      for (int off = 1; off < 32; off <<= 1){
        unsigned v = __shfl_up_sync(0xffffffffu, sc, off);
        if (lane >= off) sc += v;
      }
      unsigned excl = sc - tot;
      bool has = (excl < krem) && (krem <= sc);
      unsigned msk = __ballot_sync(0xffffffffu, has);
      int src = __ffs(msk) - 1;
      if (tid == src){
        unsigned cum = excl; unsigned bin = tid*8;
#pragma unroll
        for (int u = 0; u < 8; u++){
          if (cum + loc[u] >= krem){ bin = tid*8+u; break; }
          cum += loc[u];
        }
        s_bin = bin; s_rem = krem - cum;
      }
    }
    __syncthreads();
    unsigned bin = s_bin;
    krem = s_rem;
    prefix |= bin << shift;
    prefmask |= 0xFFu << shift;
    __syncthreads();
    if (tid < 256) s_hist[tid] = 0;   // reset for next pass (no extra barrier needed before use: next pass writes after this point, guarded by the sync above next iteration's atomics? ensure order)
    __syncthreads();
  }
  unsigned t = prefix;
  unsigned rem = krem;   // ties at t to select (index order)

  // fused selection + bce + width loss
  float bcesum = 0.0f, selsum = 0.0f, wlsum = 0.0f;
  for (int i = tid; i < NN; i += 512){
    size_t gi = (size_t)b*NN + i;
    float pos = g_pos[gi];
    unsigned key = s_key[i];
    float sel;
    if (pos > 0.5f){
      sel = 1.0f;
    } else if (key < t){
      sel = 1.0f;
    } else if (key == t){
      unsigned tr = 0;
      for (int j = 0; j < i; j++) if (s_key[j] == t) tr++;
      sel = (tr < rem) ? 1.0f : 0.0f;
    } else {
      sel = 0.0f;
    }
    float p = scores[gi];
    p = fminf(fmaxf(p, 1e-7f), 1.0f - 1e-7f);
    float bce = -(pos*logf(p) + (1.0f - pos)*logf(1.0f - p));
    bcesum += bce*sel;
    selsum += sel;

    if (pos > 0.5f){
      float w = g_wlab[gi];
      float acc = 0.0f;
#pragma unroll
      for (int kb = 0; kb < 10; kb++){
        float mh = (w >= c_lo[kb] && w < c_hi[kb]) ? 1.0f : 0.0f;
        float x = gwh[(size_t)b*10*NN + (size_t)kb*NN + i];
        float bw = fmaxf(x, 0.0f) - x*mh + log1pf(expf(-fabsf(x)));
        acc += c_wt[kb]*bw;
      }
      wlsum += acc * 0.1f;
    }
  }
#pragma unroll
  for (int off = 16; off; off >>= 1){
    bcesum += __shfl_xor_sync(0xffffffffu, bcesum, off);
    selsum += __shfl_xor_sync(0xffffffffu, selsum, off);
    wlsum  += __shfl_xor_sync(0xffffffffu, wlsum , off);
  }
  if (lane == 0){ s_red[0][warp]=bcesum; s_red[1][warp]=selsum; s_red[2][warp]=wlsum; }
  __syncthreads();
  if (tid == 0){
    double a=0, c=0, d=0;
    for (int w = 0; w < 16; w++){ a += (double)s_red[0][w]; c += (double)s_red[1][w]; d += (double)s_red[2][w]; }
    g_acc[b*8+1] = a;
    g_acc[b*8+2] = c;
    g_acc[b*8+3] = d;
  }
}

// ---------------- K3: ADD-S via 12-dim factored dot (R3 version) ----------------
// cross(P_i, G_j)  = <S_i , R_j> + <sumP_i, t_j>,  S_i[d][e] = sum_c P[i,c,d]*cp[c][e]
// cross(P_i, Gs_j) = <S'_i, R_j> + <sumP_i, t_j>,  S'_i with cps.
// Per-j smem record: 4 float4 padded to 5 (80 B stride, conflict-free LDS.128).
// warp handles 4 queries; block = 4 warps = 16 queries; j tiled 256/tile.
#define JT 256
__global__ __launch_bounds__(128) void k_adds(
    const float* __restrict__ grasps,
    const float* __restrict__ scores,
    const float* __restrict__ cp,
    const float* __restrict__ cps)
{
  __shared__ float4 sR[JT*5];
  __shared__ float  s_cp[15], s_cps[15];
  __shared__ float  s_part[4];

  int tid = threadIdx.x, lane = tid & 31, warp = tid >> 5;
  if (tid < 15){ s_cp[tid] = cp[tid]; s_cps[tid] = cps[tid]; }
  __syncthreads();

  int iBase = blockIdx.x*16;
  int b  = iBase / NN;
  int i0 = iBase + warp*4;

  float A[4][12], As[4][12], pn[4];
#pragma unroll
  for (int q = 0; q < 4; q++){
    const float* gm = grasps + (size_t)(i0+q)*16;
    float P[15];
    float pq = 0.0f;
#pragma unroll
    for (int c = 0; c < 5; c++)
#pragma unroll
      for (int d = 0; d < 3; d++){
        float v = gm[d*4+0]*s_cp[c*3+0] + gm[d*4+1]*s_cp[c*3+1] + gm[d*4+2]*s_cp[c*3+2] + gm[d*4+3];
        P[c*3+d] = v; pq += v*v;
      }
    pn[q] = pq;
#pragma unroll
    for (int d = 0; d < 3; d++){
      float s0=0, s1=0, s2=0, sp=0;
      float t0=0, t1=0, t2=0;
#pragma unroll
      for (int c = 0; c < 5; c++){
        float pv = P[c*3+d];
        s0 += pv*s_cp [c*3+0]; s1 += pv*s_cp [c*3+1]; s2 += pv*s_cp [c*3+2];
        t0 += pv*s_cps[c*3+0]; t1 += pv*s_cps[c*3+1]; t2 += pv*s_cps[c*3+2];
        sp += pv;
      }
      A [q][d*4+0]=s0; A [q][d*4+1]=s1; A [q][d*4+2]=s2; A [q][d*4+3]=sp;
      As[q][d*4+0]=t0; As[q][d*4+1]=t1; As[q][d*4+2]=t2; As[q][d*4+3]=sp;
    }
  }

  float m[4] = {3.4e38f, 3.4e38f, 3.4e38f, 3.4e38f};
  for (int t = 0; t < NN/JT; t++){
    __syncthreads();
    int jb = t*JT;
    const float4* Rp = g_rec + ((size_t)b*NN + jb)*4;
    for (int u = tid; u < JT*4; u += 128) sR[(u>>2)*5 + (u&3)] = Rp[u];
    __syncthreads();
#pragma unroll
    for (int u = 0; u < JT/32; u++){
      int jj = lane + u*32;
      float4 r0 = sR[jj*5+0];
      float4 r1 = sR[jj*5+1];
      float4 r2 = sR[jj*5+2];
      float4 r3 = sR[jj*5+3];
#pragma unroll
      for (int q = 0; q < 4; q++){
        float cA = A[q][0]*r0.x + A[q][1]*r0.y + A[q][2]*r0.z + A[q][3]*r0.w
                 + A[q][4]*r1.x + A[q][5]*r1.y + A[q][6]*r1.z + A[q][7]*r1.w
                 + A[q][8]*r2.x + A[q][9]*r2.y + A[q][10]*r2.z + A[q][11]*r2.w;
        float cS = As[q][0]*r0.x + As[q][1]*r0.y + As[q][2]*r0.z + As[q][3]*r0.w
                 + As[q][4]*r1.x + As[q][5]*r1.y + As[q][6]*r1.z + As[q][7]*r1.w
                 + As[q][8]*r2.x + As[q][9]*r2.y + As[q][10]*r2.z + As[q][11]*r2.w;
        float dG  = pn[q] + r3.x - 2.0f*cA;
        float dGs = pn[q] + r3.y - 2.0f*cS;
        m[q] = fminf(m[q], fminf(dG, dGs));
      }
    }
  }
#pragma unroll
  for (int q = 0; q < 4; q++)
#pragma unroll
    for (int off = 16; off; off >>= 1)
      m[q] = fminf(m[q], __shfl_xor_sync(0xffffffffu, m[q], off));

  if (lane == 0){
    float contrib = 0.0f;
#pragma unroll
    for (int q = 0; q < 4; q++)
      contrib += g_pos[i0+q] * sqrtf(fmaxf(m[q], 0.0f) + 1e-12f) * scores[i0+q];
    s_part[warp] = contrib;
  }
  __syncthreads();
  if (tid == 0){
    double a = 0.0;
    for (int w = 0; w < 4; w++) a += (double)s_part[w];
    atomicAdd(&g_acc[b*8+4], a);
  }
}

// ---------------- K4: finalize ----------------
__global__ void k_fin(float* __restrict__ out, int out_size){
  double bin = 0.0, wid = 0.0, adds = 0.0;
  for (int b = 0; b < BB; b++){
    double posSum = g_acc[b*8+0];
    double piv = fmax(posSum, 1.0);
    bin  += g_acc[b*8+1] / fmax(g_acc[b*8+2], 1.0);
    wid  += g_acc[b*8+3] / piv;
    adds += g_acc[b*8+4] / piv;
  }
  bin /= BB; wid /= BB; adds /= BB;
  double total = bin + wid + 3.0*adds;
  if (out_size > 0) out[0] = (float)total;
  if (out_size > 1) out[1] = (float)bin;
  if (out_size > 2) out[2] = (float)wid;
  if (out_size > 3) out[3] = (float)adds;
}

extern "C" void kernel_launch(void* const* d_in, const int* in_sizes, int n_in,
                              void* d_out, int out_size){
  const float* pred_grasps = (const float*)d_in[0];   // (4,2048,4,4)
  const float* pred_scores = (const float*)d_in[1];   // (4,2048,1)
  const float* pred_points = (const float*)d_in[2];   // (4,2048,3)
  const float* gwh         = (const float*)d_in[3];   // (4,10,2048)
  const float* pcp         = (const float*)d_in[4];   // (4,4096,3)
  const float* pcw         = (const float*)d_in[5];   // (4,4096)
  const float* pcr         = (const float*)d_in[6];   // (4,4096,3,3)
  const float* pct         = (const float*)d_in[7];   // (4,4096,3)
  const float* cp          = (const float*)d_in[8];   // (1,5,3)
  const float* cps         = (const float*)d_in[9];   // (1,5,3)

  k_prep<<<64, 256>>>(pcp);
  k_nn  <<<BB*NN/32, 256>>>(pred_points, pcw, pcr, pct, cp, cps);
  k_sel <<<BB, 512>>>(pred_scores, gwh);
  k_adds<<<BB*NN/16, 128>>>(pred_grasps, pred_scores, cp, cps);
  k_fin <<<1, 1>>>((float*)d_out, out_size);
}

// round 6
// speedup vs baseline: 1.3784x; 1.1284x over previous
// R6: 3 launches. k_prep eliminated (smem-staged contact points in k_nn, no
// zeroing anywhere — partials via plain stores). k_sel merged into the k_adds
// launch as extra blocks (runs concurrently). k_adds at Q=2/warp for 2x warps
// (occ 20%->~43%) with arithmetic identical to R3.
#include <cuda_runtime.h>
#include <math.h>

#define BB 4
#define NN 2048
#define MM 4096
#define FARV 100000.0f
#define ADDS_BLOCKS 512          // 16 queries per block

// ---------------- scratch (device globals; no allocation) ----------------
__device__ float  g_pos[BB*NN];          // success flag
__device__ float  g_pri[BB*NN];          // priority (r for negatives, +inf for positives)
__device__ float  g_wlab[BB*NN];         // gathered width label
__device__ float4 g_rec[BB*NN*4];        // (R row0,t0)(R row1,t1)(R row2,t2)(gn,gsn,0,0)
__device__ double g_acc[BB*8];           // 0 posSum, 1 bceSum, 2 selSum, 3 wlSum (plain stores by k_sel)
__device__ double g_addsPart[ADDS_BLOCKS]; // per-block adds partials (plain stores)

__constant__ float c_lo[10] = {0.0f, 0.00794435329f, 0.0158887021f, 0.0238330509f, 0.0317773996f,
                               0.0397217484f, 0.0476660972f, 0.0556104459f, 0.0635547947f, 0.0714991435f};
__constant__ float c_hi[10] = {0.00794435329f, 0.0158887021f, 0.0238330509f, 0.0317773996f, 0.0397217484f,
                               0.0476660972f, 0.0556104459f, 0.0635547947f, 0.0714991435f, 0.08f};
__constant__ float c_wt[10] = {0.16652107f, 0.21488856f, 0.37031708f, 0.55618503f, 0.75124664f,
                               0.93943357f, 1.07824539f, 1.19423112f, 1.55731375f, 2.34173634f};

// ---------------- threefry2x32 (JAX-exact, key(42), counts = iota(8192)) ----------------
__device__ __forceinline__ unsigned rotl32(unsigned x, unsigned d){ return (x<<d)|(x>>(32u-d)); }

__device__ __forceinline__ float threefry_uniform_8192(unsigned flat){
  unsigned c0, c1; bool second;
  if (flat < 4096u){ c0 = flat;        c1 = flat + 4096u; second = false; }
  else             { c0 = flat - 4096u; c1 = flat;        second = true;  }
  const unsigned ks0 = 0u, ks1 = 42u, ks2 = 0u ^ 42u ^ 0x1BD11BDAu;
  unsigned x0 = c0 + ks0, x1 = c1 + ks1;
#define TF_ROUND(r) { x0 += x1; x1 = rotl32(x1,(r)); x1 ^= x0; }
  TF_ROUND(13) TF_ROUND(15) TF_ROUND(26) TF_ROUND(6)
  x0 += ks1; x1 += ks2 + 1u;
  TF_ROUND(17) TF_ROUND(29) TF_ROUND(16) TF_ROUND(24)
  x0 += ks2; x1 += ks0 + 2u;
  TF_ROUND(13) TF_ROUND(15) TF_ROUND(26) TF_ROUND(6)
  x0 += ks0; x1 += ks1 + 3u;
  TF_ROUND(17) TF_ROUND(29) TF_ROUND(16) TF_ROUND(24)
  x0 += ks1; x1 += ks2 + 4u;
  TF_ROUND(13) TF_ROUND(15) TF_ROUND(26) TF_ROUND(6)
  x0 += ks2; x1 += ks0 + 5u;
#undef TF_ROUND
  unsigned bits = second ? x1 : x0;
  float f = __uint_as_float((bits >> 9) | 0x3F800000u) - 1.0f;
  return fmaxf(f, 0.0f);
}

// ---------------- K1: nearest neighbor (smem-staged contacts) + record ----------------
// block = 8 warps = 32 queries (batch-aligned); warp handles 4 queries.
// Dynamic smem: MM float4 (x,y,z,|c|^2) staged per block.
__global__ __launch_bounds__(256) void k_nn(
    const float* __restrict__ pred_points,
    const float* __restrict__ pcp,
    const float* __restrict__ pcw,
    const float* __restrict__ pcr,
    const float* __restrict__ pct,
    const float* __restrict__ cp,
    const float* __restrict__ cps)
{
  extern __shared__ float4 s_pc[];      // MM entries = 64KB
  __shared__ float s_cp[15], s_cps[15];
  int tid = threadIdx.x, lane = tid & 31, warp = tid >> 5;
  if (tid < 15){ s_cp[tid] = cp[tid]; s_cps[tid] = cps[tid]; }

  int q0 = (blockIdx.x*8 + warp)*4;
  int b  = q0 / NN;

  // stage contact points + norms
  {
    const float* base = pcp + (size_t)b*MM*3;
    for (int j = tid; j < MM; j += 256){
      float x = base[j*3+0], y = base[j*3+1], z = base[j*3+2];
      s_pc[j] = make_float4(x, y, z, x*x + y*y + z*z);
    }
  }
  __syncthreads();

  float qx[4], qy[4], qz[4], qn[4];
#pragma unroll
  for (int k = 0; k < 4; k++){
    const float* p = pred_points + (size_t)(q0+k)*3;
    qx[k]=p[0]; qy[k]=p[1]; qz[k]=p[2];
    qn[k]=qx[k]*qx[k]+qy[k]*qy[k]+qz[k]*qz[k];
  }
  float best[4] = {3.4e38f,3.4e38f,3.4e38f,3.4e38f};
  int   bidx[4] = {0,0,0,0};
  for (int j = lane; j < MM; j += 32){
    float4 c = s_pc[j];
#pragma unroll
    for (int k = 0; k < 4; k++){
      float dot = qx[k]*c.x + qy[k]*c.y + qz[k]*c.z;
      float d = qn[k] + c.w - 2.0f*dot;
      d = fmaxf(d, 0.0f);
      if (d < best[k]){ best[k] = d; bidx[k] = j; }
    }
  }
#pragma unroll
  for (int k = 0; k < 4; k++){
#pragma unroll
    for (int off = 16; off; off >>= 1){
      float ov = __shfl_xor_sync(0xffffffffu, best[k], off);
      int   oi = __shfl_xor_sync(0xffffffffu, bidx[k], off);
      if (ov < best[k] || (ov == best[k] && oi < bidx[k])){ best[k]=ov; bidx[k]=oi; }
    }
  }

  if (lane < 4){
    int k = lane;
    int q = q0 + k;
    int mi = bidx[k];
    float success = (best[k] < 2.5e-5f) ? 1.0f : 0.0f;  // RADIUS^2
    g_pos[q]  = success;
    g_wlab[q] = pcw[(size_t)b*MM + mi];
    float r = threefry_uniform_8192((unsigned)q);
    g_pri[q] = (success > 0.5f) ? __int_as_float(0x7f800000) : r;

    float Rm[9], Tv[3];
    if (success > 0.5f){
      const float* rp = pcr + ((size_t)b*MM + mi)*9;
#pragma unroll
      for (int u = 0; u < 9; u++) Rm[u] = rp[u];
      const float* tp = pct + ((size_t)b*MM + mi)*3;
      Tv[0]=tp[0]; Tv[1]=tp[1]; Tv[2]=tp[2];
    } else {
#pragma unroll
      for (int u = 0; u < 9; u++) Rm[u] = FARV;
      Tv[0]=FARV; Tv[1]=FARV; Tv[2]=FARV;
    }
    float gn = 0.0f, gsn = 0.0f;
#pragma unroll
    for (int c = 0; c < 5; c++){
#pragma unroll
      for (int d = 0; d < 3; d++){
        float v  = Rm[d*3+0]*s_cp [c*3+0] + Rm[d*3+1]*s_cp [c*3+1] + Rm[d*3+2]*s_cp [c*3+2] + Tv[d];
        float vs = Rm[d*3+0]*s_cps[c*3+0] + Rm[d*3+1]*s_cps[c*3+1] + Rm[d*3+2]*s_cps[c*3+2] + Tv[d];
        gn  += v*v;
        gsn += vs*vs;
      }
    }
    float4* rec = g_rec + (size_t)q*4;
    rec[0] = make_float4(Rm[0], Rm[1], Rm[2], Tv[0]);
    rec[1] = make_float4(Rm[3], Rm[4], Rm[5], Tv[1]);
    rec[2] = make_float4(Rm[6], Rm[7], Rm[8], Tv[2]);
    rec[3] = make_float4(gn, gsn, 0.0f, 0.0f);
  }
}

// ---------------- K2: merged ADD-S (blocks 0..511) + selection (blocks 512..515) ----------------
#define JT 256
__global__ __launch_bounds__(256) void k_main(
    const float* __restrict__ grasps,
    const float* __restrict__ scores,
    const float* __restrict__ gwh,
    const float* __restrict__ cp,
    const float* __restrict__ cps)
{
  __shared__ float4 sR[JT*5];                  // adds tile (20KB)
  __shared__ unsigned s_key[NN];               // sel keys (8KB)
  __shared__ unsigned s_hist[256];
  __shared__ unsigned s_bin, s_rem;
  __shared__ float    s_red[4][8];
  __shared__ float    s_cp[15], s_cps[15], s_part[8];

  int tid = threadIdx.x, lane = tid & 31, warp = tid >> 5;

  if (blockIdx.x < ADDS_BLOCKS){
    // ================= ADD-S role: 16 queries per block, Q=2 per warp =================
    if (tid < 15){ s_cp[tid] = cp[tid]; s_cps[tid] = cps[tid]; }
    __syncthreads();

    int iBase = blockIdx.x*16;
    int b  = iBase / NN;
    int i0 = iBase + warp*2;

    float A[2][12], As[2][12], pn[2];
#pragma unroll
    for (int q = 0; q < 2; q++){
      const float* gm = grasps + (size_t)(i0+q)*16;
      float P[15];
      float pq = 0.0f;
#pragma unroll
      for (int c = 0; c < 5; c++)
#pragma unroll
        for (int d = 0; d < 3; d++){
          float v = gm[d*4+0]*s_cp[c*3+0] + gm[d*4+1]*s_cp[c*3+1] + gm[d*4+2]*s_cp[c*3+2] + gm[d*4+3];
          P[c*3+d] = v; pq += v*v;
        }
      pn[q] = pq;
#pragma unroll
      for (int d = 0; d < 3; d++){
        float s0=0, s1=0, s2=0, sp=0;
        float t0=0, t1=0, t2=0;
#pragma unroll
        for (int c = 0; c < 5; c++){
          float pv = P[c*3+d];
          s0 += pv*s_cp [c*3+0]; s1 += pv*s_cp [c*3+1]; s2 += pv*s_cp [c*3+2];
          t0 += pv*s_cps[c*3+0]; t1 += pv*s_cps[c*3+1]; t2 += pv*s_cps[c*3+2];
          sp += pv;
        }
        A [q][d*4+0]=s0; A [q][d*4+1]=s1; A [q][d*4+2]=s2; A [q][d*4+3]=sp;
        As[q][d*4+0]=t0; As[q][d*4+1]=t1; As[q][d*4+2]=t2; As[q][d*4+3]=sp;
      }
    }

    float m[2] = {3.4e38f, 3.4e38f};
    for (int t = 0; t < NN/JT; t++){
      __syncthreads();
      int jb = t*JT;
      const float4* Rp = g_rec + ((size_t)b*NN + jb)*4;
      for (int u = tid; u < JT*4; u += 256) sR[(u>>2)*5 + (u&3)] = Rp[u];
      __syncthreads();
#pragma unroll
      for (int u = 0; u < JT/32; u++){
        int jj = lane + u*32;
        float4 r0 = sR[jj*5+0];
        float4 r1 = sR[jj*5+1];
        float4 r2 = sR[jj*5+2];
        float4 r3 = sR[jj*5+3];
#pragma unroll
        for (int q = 0; q < 2; q++){
          float cA = A[q][0]*r0.x + A[q][1]*r0.y + A[q][2]*r0.z + A[q][3]*r0.w
                   + A[q][4]*r1.x + A[q][5]*r1.y + A[q][6]*r1.z + A[q][7]*r1.w
                   + A[q][8]*r2.x + A[q][9]*r2.y + A[q][10]*r2.z + A[q][11]*r2.w;
          float cS = As[q][0]*r0.x + As[q][1]*r0.y + As[q][2]*r0.z + As[q][3]*r0.w
                   + As[q][4]*r1.x + As[q][5]*r1.y + As[q][6]*r1.z + As[q][7]*r1.w
                   + As[q][8]*r2.x + As[q][9]*r2.y + As[q][10]*r2.z + As[q][11]*r2.w;
          float dG  = pn[q] + r3.x - 2.0f*cA;
          float dGs = pn[q] + r3.y - 2.0f*cS;
          m[q] = fminf(m[q], fminf(dG, dGs));
        }
      }
    }
#pragma unroll
    for (int q = 0; q < 2; q++)
#pragma unroll
      for (int off = 16; off; off >>= 1)
        m[q] = fminf(m[q], __shfl_xor_sync(0xffffffffu, m[q], off));

    if (lane == 0){
      float contrib = 0.0f;
#pragma unroll
      for (int q = 0; q < 2; q++)
        contrib += g_pos[i0+q] * sqrtf(fmaxf(m[q], 0.0f) + 1e-12f) * scores[i0+q];
      s_part[warp] = contrib;
    }
    __syncthreads();
    if (tid == 0){
      double a = 0.0;
      for (int w = 0; w < 8; w++) a += (double)s_part[w];
      g_addsPart[blockIdx.x] = a;   // plain store — no zeroing needed
    }
  } else {
    // ================= selection role: one block per batch =================
    int b = blockIdx.x - ADDS_BLOCKS;

    float possum = 0.0f;
    for (int i = tid; i < NN; i += 256){
      float pos = g_pos[(size_t)b*NN + i];
      float pri = g_pri[(size_t)b*NN + i];
      s_key[i] = (pos > 0.5f) ? 0xFFFFFFFFu : __float_as_uint(pri);
      possum += pos;
    }
#pragma unroll
    for (int off = 16; off; off >>= 1) possum += __shfl_xor_sync(0xffffffffu, possum, off);
    if (lane == 0) s_red[3][warp] = possum;
    __syncthreads();
    double nPos = 0.0;
    for (int w = 0; w < 8; w++) nPos += (double)s_red[3][w];
    unsigned kk = (nPos > 0.0) ? (unsigned)nPos : 2u;

    unsigned prefix = 0, prefmask = 0, krem = kk;
#pragma unroll
    for (int pass = 0; pass < 4; pass++){
      int shift = 24 - pass*8;
      s_hist[tid] = 0;
      __syncthreads();
      for (int i = tid; i < NN; i += 256){
        unsigned key = s_key[i];
        if ((key & prefmask) == prefix) atomicAdd(&s_hist[(key >> shift) & 0xFFu], 1u);
      }
      __syncthreads();
      if (tid < 32){
        unsigned loc[8]; unsigned tot = 0;
#pragma unroll
        for (int u = 0; u < 8; u++){ loc[u] = s_hist[tid*8+u]; tot += loc[u]; }
        unsigned sc = tot;
#pragma unroll
        for (int off = 1; off < 32; off <<= 1){
          unsigned v = __shfl_up_sync(0xffffffffu, sc, off);
          if (lane >= off) sc += v;
        }
        unsigned excl = sc - tot;
        bool has = (excl < krem) && (krem <= sc);
        unsigned msk = __ballot_sync(0xffffffffu, has);
        int src = __ffs(msk) - 1;
        if (tid == src){
          unsigned cum = excl; unsigned bin = tid*8;
#pragma unroll
          for (int u = 0; u < 8; u++){
            if (cum + loc[u] >= krem){ bin = tid*8+u; break; }
            cum += loc[u];
          }
          s_bin = bin; s_rem = krem - cum;
        }
      }
      __syncthreads();
      unsigned bin = s_bin;
      krem = s_rem;
      prefix |= bin << shift;
      prefmask |= 0xFFu << shift;
      __syncthreads();
    }
    unsigned t = prefix;
    unsigned rem = krem;   // ties at t to select (index order)

    float bcesum = 0.0f, selsum = 0.0f, wlsum = 0.0f;
    for (int i = tid; i < NN; i += 256){
      size_t gi = (size_t)b*NN + i;
      float pos = g_pos[gi];
      unsigned key = s_key[i];
      float sel;
      if (pos > 0.5f){
        sel = 1.0f;
      } else if (key < t){
        sel = 1.0f;
      } else if (key == t){
        unsigned tr = 0;
        for (int j = 0; j < i; j++) if (s_key[j] == t) tr++;
        sel = (tr < rem) ? 1.0f : 0.0f;
      } else {
        sel = 0.0f;
      }
      float p = scores[gi];
      p = fminf(fmaxf(p, 1e-7f), 1.0f - 1e-7f);
      float bce = -(pos*logf(p) + (1.0f - pos)*logf(1.0f - p));
      bcesum += bce*sel;
      selsum += sel;

      if (pos > 0.5f){
        float w = g_wlab[gi];
        float acc = 0.0f;
#pragma unroll
        for (int kb = 0; kb < 10; kb++){
          float mh = (w >= c_lo[kb] && w < c_hi[kb]) ? 1.0f : 0.0f;
          float x = gwh[(size_t)b*10*NN + (size_t)kb*NN + i];
          float bw = fmaxf(x, 0.0f) - x*mh + log1pf(expf(-fabsf(x)));
          acc += c_wt[kb]*bw;
        }
        wlsum += acc * 0.1f;
      }
    }
#pragma unroll
    for (int off = 16; off; off >>= 1){
      bcesum += __shfl_xor_sync(0xffffffffu, bcesum, off);
      selsum += __shfl_xor_sync(0xffffffffu, selsum, off);
      wlsum  += __shfl_xor_sync(0xffffffffu, wlsum , off);
    }
    if (lane == 0){ s_red[0][warp]=bcesum; s_red[1][warp]=selsum; s_red[2][warp]=wlsum; }
    __syncthreads();
    if (tid == 0){
      double a=0, c=0, d=0;
      for (int w = 0; w < 8; w++){ a += (double)s_red[0][w]; c += (double)s_red[1][w]; d += (double)s_red[2][w]; }
      g_acc[b*8+0] = nPos;
      g_acc[b*8+1] = a;
      g_acc[b*8+2] = c;
      g_acc[b*8+3] = d;
    }
  }
}

// ---------------- K3: finalize (reduce adds partials + output) ----------------
__global__ __launch_bounds__(256) void k_fin(float* __restrict__ out, int out_size){
  __shared__ double s_d[256];
  int tid = threadIdx.x;
  // pair up partials: indices 2t, 2t+1 are in the same batch (128 per batch)
  double v = g_addsPart[2*tid] + g_addsPart[2*tid+1];
  s_d[tid] = v;
  __syncthreads();
  // reduce within each 64-thread group (one batch each)
#pragma unroll
  for (int off = 32; off; off >>= 1){
    if ((tid & 63) < off) s_d[tid] += s_d[tid + off];
    __syncthreads();
  }
  if (tid == 0){
    double bin = 0.0, wid = 0.0, adds = 0.0;
    for (int b = 0; b < BB; b++){
      double posSum = g_acc[b*8+0];
      double piv = fmax(posSum, 1.0);
      bin  += g_acc[b*8+1] / fmax(g_acc[b*8+2], 1.0);
      wid  += g_acc[b*8+3] / piv;
      adds += s_d[b*64] / piv;
    }
    bin /= BB; wid /= BB; adds /= BB;
    double total = bin + wid + 3.0*adds;
    if (out_size > 0) out[0] = (float)total;
    if (out_size > 1) out[1] = (float)bin;
    if (out_size > 2) out[2] = (float)wid;
    if (out_size > 3) out[3] = (float)adds;
  }
}

extern "C" void kernel_launch(void* const* d_in, const int* in_sizes, int n_in,
                              void* d_out, int out_size){
  const float* pred_grasps = (const float*)d_in[0];   // (4,2048,4,4)
  const float* pred_scores = (const float*)d_in[1];   // (4,2048,1)
  const float* pred_points = (const float*)d_in[2];   // (4,2048,3)
  const float* gwh         = (const float*)d_in[3];   // (4,10,2048)
  const float* pcp         = (const float*)d_in[4];   // (4,4096,3)
  const float* pcw         = (const float*)d_in[5];   // (4,4096)
  const float* pcr         = (const float*)d_in[6];   // (4,4096,3,3)
  const float* pct         = (const float*)d_in[7];   // (4,4096,3)
  const float* cp          = (const float*)d_in[8];   // (1,5,3)
  const float* cps         = (const float*)d_in[9];   // (1,5,3)

  static bool attr_done = false;
  if (!attr_done){
    cudaFuncSetAttribute(k_nn, cudaFuncAttributeMaxDynamicSharedMemorySize,
                         MM*(int)sizeof(float4));
    attr_done = true;
  }

  k_nn  <<<BB*NN/32, 256, MM*sizeof(float4)>>>(pred_points, pcp, pcw, pcr, pct, cp, cps);
  k_main<<<ADDS_BLOCKS + BB, 256>>>(pred_grasps, pred_scores, gwh, cp, cps);
  k_fin <<<1, 256>>>((float*)d_out, out_size);
}

// round 7
// speedup vs baseline: 1.4566x; 1.0567x over previous
// R7: k_nn split into a 4-way j-domain partial scan (grid 1024, 16KB smem,
// packed u64 (d,j) partials preserving first-argmin ties) + a per-query
// combine/record kernel. k_main (adds Q=2 + merged radix sel) and k_fin as R6.
#include <cuda_runtime.h>
#include <math.h>

#define BB 4
#define NN 2048
#define MM 4096
#define NSPLIT 4
#define MSPL (MM/NSPLIT)         // 1024 contacts per split
#define FARV 100000.0f
#define ADDS_BLOCKS 512          // 16 queries per block

typedef unsigned long long u64;

// ---------------- scratch (device globals; no allocation) ----------------
__device__ u64    g_nnPart[BB*NN*NSPLIT]; // packed (d_bits<<32)|j partial argmins
__device__ float  g_pos[BB*NN];
__device__ float  g_pri[BB*NN];
__device__ float  g_wlab[BB*NN];
__device__ float4 g_rec[BB*NN*4];        // (R row0,t0)(R row1,t1)(R row2,t2)(gn,gsn,0,0)
__device__ double g_acc[BB*8];           // 0 posSum, 1 bceSum, 2 selSum, 3 wlSum (plain stores)
__device__ double g_addsPart[ADDS_BLOCKS];

__constant__ float c_lo[10] = {0.0f, 0.00794435329f, 0.0158887021f, 0.0238330509f, 0.0317773996f,
                               0.0397217484f, 0.0476660972f, 0.0556104459f, 0.0635547947f, 0.0714991435f};
__constant__ float c_hi[10] = {0.00794435329f, 0.0158887021f, 0.0238330509f, 0.0317773996f, 0.0397217484f,
                               0.0476660972f, 0.0556104459f, 0.0635547947f, 0.0714991435f, 0.08f};
__constant__ float c_wt[10] = {0.16652107f, 0.21488856f, 0.37031708f, 0.55618503f, 0.75124664f,
                               0.93943357f, 1.07824539f, 1.19423112f, 1.55731375f, 2.34173634f};

// ---------------- threefry2x32 (JAX-exact, key(42), counts = iota(8192)) ----------------
__device__ __forceinline__ unsigned rotl32(unsigned x, unsigned d){ return (x<<d)|(x>>(32u-d)); }

__device__ __forceinline__ float threefry_uniform_8192(unsigned flat){
  unsigned c0, c1; bool second;
  if (flat < 4096u){ c0 = flat;        c1 = flat + 4096u; second = false; }
  else             { c0 = flat - 4096u; c1 = flat;        second = true;  }
  const unsigned ks0 = 0u, ks1 = 42u, ks2 = 0u ^ 42u ^ 0x1BD11BDAu;
  unsigned x0 = c0 + ks0, x1 = c1 + ks1;
#define TF_ROUND(r) { x0 += x1; x1 = rotl32(x1,(r)); x1 ^= x0; }
  TF_ROUND(13) TF_ROUND(15) TF_ROUND(26) TF_ROUND(6)
  x0 += ks1; x1 += ks2 + 1u;
  TF_ROUND(17) TF_ROUND(29) TF_ROUND(16) TF_ROUND(24)
  x0 += ks2; x1 += ks0 + 2u;
  TF_ROUND(13) TF_ROUND(15) TF_ROUND(26) TF_ROUND(6)
  x0 += ks0; x1 += ks1 + 3u;
  TF_ROUND(17) TF_ROUND(29) TF_ROUND(16) TF_ROUND(24)
  x0 += ks1; x1 += ks2 + 4u;
  TF_ROUND(13) TF_ROUND(15) TF_ROUND(26) TF_ROUND(6)
  x0 += ks2; x1 += ks0 + 5u;
#undef TF_ROUND
  unsigned bits = second ? x1 : x0;
  float f = __uint_as_float((bits >> 9) | 0x3F800000u) - 1.0f;
  return fmaxf(f, 0.0f);
}

// ---------------- K1a: partial NN scan over a quarter of contacts ----------------
// blockIdx.x = qgroup*NSPLIT + split; block = 8 warps = 32 queries.
__global__ __launch_bounds__(256) void k_nn1(
    const float* __restrict__ pred_points,
    const float* __restrict__ pcp)
{
  __shared__ float4 s_pc[MSPL];     // 16KB
  int tid = threadIdx.x, lane = tid & 31, warp = tid >> 5;
  int split  = blockIdx.x & (NSPLIT-1);
  int qgroup = blockIdx.x >> 2;
  int q0 = (qgroup*8 + warp)*4;
  int b  = q0 / NN;
  int jb = split*MSPL;

  {
    const float* base = pcp + ((size_t)b*MM + jb)*3;
    for (int j = tid; j < MSPL; j += 256){
      float x = base[j*3+0], y = base[j*3+1], z = base[j*3+2];
      s_pc[j] = make_float4(x, y, z, x*x + y*y + z*z);
    }
  }
  __syncthreads();

  float qx[4], qy[4], qz[4], qn[4];
#pragma unroll
  for (int k = 0; k < 4; k++){
    const float* p = pred_points + (size_t)(q0+k)*3;
    qx[k]=p[0]; qy[k]=p[1]; qz[k]=p[2];
    qn[k]=qx[k]*qx[k]+qy[k]*qy[k]+qz[k]*qz[k];
  }
  float best[4] = {3.4e38f,3.4e38f,3.4e38f,3.4e38f};
  int   bidx[4] = {0,0,0,0};
  for (int j = lane; j < MSPL; j += 32){
    float4 c = s_pc[j];
#pragma unroll
    for (int k = 0; k < 4; k++){
      float dot = qx[k]*c.x + qy[k]*c.y + qz[k]*c.z;
      float d = qn[k] + c.w - 2.0f*dot;
      d = fmaxf(d, 0.0f);
      if (d < best[k]){ best[k] = d; bidx[k] = j; }
    }
  }
  // pack (d, global_j) and u64-min reduce: lexicographic == (min d, then min j)
#pragma unroll
  for (int k = 0; k < 4; k++){
    u64 key = ((u64)__float_as_uint(best[k]) << 32) | (unsigned)(jb + bidx[k]);
#pragma unroll
    for (int off = 16; off; off >>= 1){
      u64 o = __shfl_xor_sync(0xffffffffu, key, off);
      if (o < key) key = o;
    }
    if (lane == k) g_nnPart[(size_t)(q0+k)*NSPLIT + split] = key;
  }
}

// ---------------- K1b: combine partials + threefry + record ----------------
// one thread per query.
__global__ __launch_bounds__(256) void k_nn2(
    const float* __restrict__ pcw,
    const float* __restrict__ pcr,
    const float* __restrict__ pct,
    const float* __restrict__ cp,
    const float* __restrict__ cps)
{
  __shared__ float s_cp[15], s_cps[15];
  int tid = threadIdx.x;
  if (tid < 15){ s_cp[tid] = cp[tid]; s_cps[tid] = cps[tid]; }
  __syncthreads();

  int q = blockIdx.x*256 + tid;
  int b = q / NN;

  const u64* part = g_nnPart + (size_t)q*NSPLIT;
  u64 key = part[0];
#pragma unroll
  for (int s = 1; s < NSPLIT; s++){ u64 o = part[s]; if (o < key) key = o; }
  float d = __uint_as_float((unsigned)(key >> 32));
  int  mi = (int)(key & 0xFFFFFFFFu);

  float success = (d < 2.5e-5f) ? 1.0f : 0.0f;   // RADIUS^2
  g_pos[q]  = success;
  g_wlab[q] = pcw[(size_t)b*MM + mi];
  float r = threefry_uniform_8192((unsigned)q);
  g_pri[q] = (success > 0.5f) ? __int_as_float(0x7f800000) : r;

  float Rm[9], Tv[3];
  if (success > 0.5f){
    const float* rp = pcr + ((size_t)b*MM + mi)*9;
#pragma unroll
    for (int u = 0; u < 9; u++) Rm[u] = rp[u];
    const float* tp = pct + ((size_t)b*MM + mi)*3;
    Tv[0]=tp[0]; Tv[1]=tp[1]; Tv[2]=tp[2];
  } else {
#pragma unroll
    for (int u = 0; u < 9; u++) Rm[u] = FARV;
    Tv[0]=FARV; Tv[1]=FARV; Tv[2]=FARV;
  }
  float gn = 0.0f, gsn = 0.0f;
#pragma unroll
  for (int c = 0; c < 5; c++){
#pragma unroll
    for (int d2 = 0; d2 < 3; d2++){
      float v  = Rm[d2*3+0]*s_cp [c*3+0] + Rm[d2*3+1]*s_cp [c*3+1] + Rm[d2*3+2]*s_cp [c*3+2] + Tv[d2];
      float vs = Rm[d2*3+0]*s_cps[c*3+0] + Rm[d2*3+1]*s_cps[c*3+1] + Rm[d2*3+2]*s_cps[c*3+2] + Tv[d2];
      gn  += v*v;
      gsn += vs*vs;
    }
  }
  float4* rec = g_rec + (size_t)q*4;
  rec[0] = make_float4(Rm[0], Rm[1], Rm[2], Tv[0]);
  rec[1] = make_float4(Rm[3], Rm[4], Rm[5], Tv[1]);
  rec[2] = make_float4(Rm[6], Rm[7], Rm[8], Tv[2]);
  rec[3] = make_float4(gn, gsn, 0.0f, 0.0f);
}

// ---------------- K2: merged ADD-S (blocks 0..511) + selection (blocks 512..515) ----------------
#define JT 256
__global__ __launch_bounds__(256) void k_main(
    const float* __restrict__ grasps,
    const float* __restrict__ scores,
    const float* __restrict__ gwh,
    const float* __restrict__ cp,
    const float* __restrict__ cps)
{
  __shared__ float4 sR[JT*5];                  // adds tile (20KB)
  __shared__ unsigned s_key[NN];               // sel keys (8KB)
  __shared__ unsigned s_hist[256];
  __shared__ unsigned s_bin, s_rem;
  __shared__ float    s_red[4][8];
  __shared__ float    s_cp[15], s_cps[15], s_part[8];

  int tid = threadIdx.x, lane = tid & 31, warp = tid >> 5;

  if (blockIdx.x < ADDS_BLOCKS){
    // ================= ADD-S role: 16 queries per block, Q=2 per warp =================
    if (tid < 15){ s_cp[tid] = cp[tid]; s_cps[tid] = cps[tid]; }
    __syncthreads();

    int iBase = blockIdx.x*16;
    int b  = iBase / NN;
    int i0 = iBase + warp*2;

    float A[2][12], As[2][12], pn[2];
#pragma unroll
    for (int q = 0; q < 2; q++){
      const float* gm = grasps + (size_t)(i0+q)*16;
      float P[15];
      float pq = 0.0f;
#pragma unroll
      for (int c = 0; c < 5; c++)
#pragma unroll
        for (int d = 0; d < 3; d++){
          float v = gm[d*4+0]*s_cp[c*3+0] + gm[d*4+1]*s_cp[c*3+1] + gm[d*4+2]*s_cp[c*3+2] + gm[d*4+3];
          P[c*3+d] = v; pq += v*v;
        }
      pn[q] = pq;
#pragma unroll
      for (int d = 0; d < 3; d++){
        float s0=0, s1=0, s2=0, sp=0;
        float t0=0, t1=0, t2=0;
#pragma unroll
        for (int c = 0; c < 5; c++){
          float pv = P[c*3+d];
          s0 += pv*s_cp [c*3+0]; s1 += pv*s_cp [c*3+1]; s2 += pv*s_cp [c*3+2];
          t0 += pv*s_cps[c*3+0]; t1 += pv*s_cps[c*3+1]; t2 += pv*s_cps[c*3+2];
          sp += pv;
        }
        A [q][d*4+0]=s0; A [q][d*4+1]=s1; A [q][d*4+2]=s2; A [q][d*4+3]=sp;
        As[q][d*4+0]=t0; As[q][d*4+1]=t1; As[q][d*4+2]=t2; As[q][d*4+3]=sp;
      }
    }

    float m[2] = {3.4e38f, 3.4e38f};
    for (int t = 0; t < NN/JT; t++){
      __syncthreads();
      int jb = t*JT;
      const float4* Rp = g_rec + ((size_t)b*NN + jb)*4;
      for (int u = tid; u < JT*4; u += 256) sR[(u>>2)*5 + (u&3)] = Rp[u];
      __syncthreads();
#pragma unroll
      for (int u = 0; u < JT/32; u++){
        int jj = lane + u*32;
        float4 r0 = sR[jj*5+0];
        float4 r1 = sR[jj*5+1];
        float4 r2 = sR[jj*5+2];
        float4 r3 = sR[jj*5+3];
#pragma unroll
        for (int q = 0; q < 2; q++){
          float cA = A[q][0]*r0.x + A[q][1]*r0.y + A[q][2]*r0.z + A[q][3]*r0.w
                   + A[q][4]*r1.x + A[q][5]*r1.y + A[q][6]*r1.z + A[q][7]*r1.w
                   + A[q][8]*r2.x + A[q][9]*r2.y + A[q][10]*r2.z + A[q][11]*r2.w;
          float cS = As[q][0]*r0.x + As[q][1]*r0.y + As[q][2]*r0.z + As[q][3]*r0.w
                   + As[q][4]*r1.x + As[q][5]*r1.y + As[q][6]*r1.z + As[q][7]*r1.w
                   + As[q][8]*r2.x + As[q][9]*r2.y + As[q][10]*r2.z + As[q][11]*r2.w;
          float dG  = pn[q] + r3.x - 2.0f*cA;
          float dGs = pn[q] + r3.y - 2.0f*cS;
          m[q] = fminf(m[q], fminf(dG, dGs));
        }
      }
    }
#pragma unroll
    for (int q = 0; q < 2; q++)
#pragma unroll
      for (int off = 16; off; off >>= 1)
        m[q] = fminf(m[q], __shfl_xor_sync(0xffffffffu, m[q], off));

    if (lane == 0){
      float contrib = 0.0f;
#pragma unroll
      for (int q = 0; q < 2; q++)
        contrib += g_pos[i0+q] * sqrtf(fmaxf(m[q], 0.0f) + 1e-12f) * scores[i0+q];
      s_part[warp] = contrib;
    }
    __syncthreads();
    if (tid == 0){
      double a = 0.0;
      for (int w = 0; w < 8; w++) a += (double)s_part[w];
      g_addsPart[blockIdx.x] = a;   // plain store — no zeroing needed
    }
  } else {
    // ================= selection role: one block per batch =================
    int b = blockIdx.x - ADDS_BLOCKS;

    float possum = 0.0f;
    for (int i = tid; i < NN; i += 256){
      float pos = g_pos[(size_t)b*NN + i];
      float pri = g_pri[(size_t)b*NN + i];
      s_key[i] = (pos > 0.5f) ? 0xFFFFFFFFu : __float_as_uint(pri);
      possum += pos;
    }
#pragma unroll
    for (int off = 16; off; off >>= 1) possum += __shfl_xor_sync(0xffffffffu, possum, off);
    if (lane == 0) s_red[3][warp] = possum;
    __syncthreads();
    double nPos = 0.0;
    for (int w = 0; w < 8; w++) nPos += (double)s_red[3][w];
    unsigned kk = (nPos > 0.0) ? (unsigned)nPos : 2u;

    unsigned prefix = 0, prefmask = 0, krem = kk;
#pragma unroll
    for (int pass = 0; pass < 4; pass++){
      int shift = 24 - pass*8;
      s_hist[tid] = 0;
      __syncthreads();
      for (int i = tid; i < NN; i += 256){
        unsigned key = s_key[i];
        if ((key & prefmask) == prefix) atomicAdd(&s_hist[(key >> shift) & 0xFFu], 1u);
      }
      __syncthreads();
      if (tid < 32){
        unsigned loc[8]; unsigned tot = 0;
#pragma unroll
        for (int u = 0; u < 8; u++){ loc[u] = s_hist[tid*8+u]; tot += loc[u]; }
        unsigned sc = tot;
#pragma unroll
        for (int off = 1; off < 32; off <<= 1){
          unsigned v = __shfl_up_sync(0xffffffffu, sc, off);
          if (lane >= off) sc += v;
        }
        unsigned excl = sc - tot;
        bool has = (excl < krem) && (krem <= sc);
        unsigned msk = __ballot_sync(0xffffffffu, has);
        int src = __ffs(msk) - 1;
        if (tid == src){
          unsigned cum = excl; unsigned bin = tid*8;
#pragma unroll
          for (int u = 0; u < 8; u++){
            if (cum + loc[u] >= krem){ bin = tid*8+u; break; }
            cum += loc[u];
          }
          s_bin = bin; s_rem = krem - cum;
        }
      }
      __syncthreads();
      unsigned bin = s_bin;
      krem = s_rem;
      prefix |= bin << shift;
      prefmask |= 0xFFu << shift;
      __syncthreads();
    }
    unsigned t = prefix;
    unsigned rem = krem;   // ties at t to select (index order)

    float bcesum = 0.0f, selsum = 0.0f, wlsum = 0.0f;
    for (int i = tid; i < NN; i += 256){
      size_t gi = (size_t)b*NN + i;
      float pos = g_pos[gi];
      unsigned key = s_key[i];
      float sel;
      if (pos > 0.5f){
        sel = 1.0f;
      } else if (key < t){
        sel = 1.0f;
      } else if (key == t){
        unsigned tr = 0;
        for (int j = 0; j < i; j++) if (s_key[j] == t) tr++;
        sel = (tr < rem) ? 1.0f : 0.0f;
      } else {
        sel = 0.0f;
      }
      float p = scores[gi];
      p = fminf(fmaxf(p, 1e-7f), 1.0f - 1e-7f);
      float bce = -(pos*logf(p) + (1.0f - pos)*logf(1.0f - p));
      bcesum += bce*sel;
      selsum += sel;

      if (pos > 0.5f){
        float w = g_wlab[gi];
        float acc = 0.0f;
#pragma unroll
        for (int kb = 0; kb < 10; kb++){
          float mh = (w >= c_lo[kb] && w < c_hi[kb]) ? 1.0f : 0.0f;
          float x = gwh[(size_t)b*10*NN + (size_t)kb*NN + i];
          float bw = fmaxf(x, 0.0f) - x*mh + log1pf(expf(-fabsf(x)));
          acc += c_wt[kb]*bw;
        }
        wlsum += acc * 0.1f;
      }
    }
#pragma unroll
    for (int off = 16; off; off >>= 1){
      bcesum += __shfl_xor_sync(0xffffffffu, bcesum, off);
      selsum += __shfl_xor_sync(0xffffffffu, selsum, off);
      wlsum  += __shfl_xor_sync(0xffffffffu, wlsum , off);
    }
    if (lane == 0){ s_red[0][warp]=bcesum; s_red[1][warp]=selsum; s_red[2][warp]=wlsum; }
    __syncthreads();
    if (tid == 0){
      double a=0, c=0, d=0;
      for (int w = 0; w < 8; w++){ a += (double)s_red[0][w]; c += (double)s_red[1][w]; d += (double)s_red[2][w]; }
      g_acc[b*8+0] = nPos;
      g_acc[b*8+1] = a;
      g_acc[b*8+2] = c;
      g_acc[b*8+3] = d;
    }
  }
}

// ---------------- K3: finalize (reduce adds partials + output) ----------------
__global__ __launch_bounds__(256) void k_fin(float* __restrict__ out, int out_size){
  __shared__ double s_d[256];
  int tid = threadIdx.x;
  double v = g_addsPart[2*tid] + g_addsPart[2*tid+1];
  s_d[tid] = v;
  __syncthreads();
#pragma unroll
  for (int off = 32; off; off >>= 1){
    if ((tid & 63) < off) s_d[tid] += s_d[tid + off];
    __syncthreads();
  }
  if (tid == 0){
    double bin = 0.0, wid = 0.0, adds = 0.0;
    for (int b = 0; b < BB; b++){
      double posSum = g_acc[b*8+0];
      double piv = fmax(posSum, 1.0);
      bin  += g_acc[b*8+1] / fmax(g_acc[b*8+2], 1.0);
      wid  += g_acc[b*8+3] / piv;
      adds += s_d[b*64] / piv;
    }
    bin /= BB; wid /= BB; adds /= BB;
    double total = bin + wid + 3.0*adds;
    if (out_size > 0) out[0] = (float)total;
    if (out_size > 1) out[1] = (float)bin;
    if (out_size > 2) out[2] = (float)wid;
    if (out_size > 3) out[3] = (float)adds;
  }
}

extern "C" void kernel_launch(void* const* d_in, const int* in_sizes, int n_in,
                              void* d_out, int out_size){
  const float* pred_grasps = (const float*)d_in[0];   // (4,2048,4,4)
  const float* pred_scores = (const float*)d_in[1];   // (4,2048,1)
  const float* pred_points = (const float*)d_in[2];   // (4,2048,3)
  const float* gwh         = (const float*)d_in[3];   // (4,10,2048)
  const float* pcp         = (const float*)d_in[4];   // (4,4096,3)
  const float* pcw         = (const float*)d_in[5];   // (4,4096)
  const float* pcr         = (const float*)d_in[6];   // (4,4096,3,3)
  const float* pct         = (const float*)d_in[7];   // (4,4096,3)
  const float* cp          = (const float*)d_in[8];   // (1,5,3)
  const float* cps         = (const float*)d_in[9];   // (1,5,3)

  k_nn1 <<<(BB*NN/32)*NSPLIT, 256>>>(pred_points, pcp);
  k_nn2 <<<BB*NN/256, 256>>>(pcw, pcr, pct, cp, cps);
  k_main<<<ADDS_BLOCKS + BB, 256>>>(pred_grasps, pred_scores, gwh, cp, cps);
  k_fin <<<1, 256>>>((float*)d_out, out_size);
}